// round 10
// baseline (speedup 1.0000x reference)
#include <cuda_runtime.h>
#include <cstdint>

#define NN      12000
#define HID     32
#define TSTEPS  50
#define TM      128
#define KSPLIT  3
#define KITEM   4000             // K per work item (KSPLIT*KITEM == NN)
#define NCHUNK  125              // KITEM / 32
#define NBLK    94               // ceil(12000/128)
#define NITEMS  (NBLK * KSPLIT)  // 282 CTAs, one item each
#define NSTAGES 5
#define NT      5                // n-tiles: cols 0..39 (z: 0..31, a_t: 32, pad: 33..39)
#define NCOLS   40
#define BSTRIDE 160              // B row stride in bytes (16-aligned, conflict-free)
#define BOFF    16384            // B region offset within a stage
#define STAGE_BYTES (16384 + 32 * BSTRIDE)   // 21504
#define SMEM_REQ (NSTAGES * STAGE_BYTES)     // 107520

__device__ float g_part[KSPLIT * NN * NCOLS];   // split-K partials of adj@[z|a_t]

// ---------------------------------------------------------------------------
// Stage load: A = adj tile (swizzled, line-complete warp-ops);
//             B = z rows (direct, contiguous) + a_t gather column.
// ---------------------------------------------------------------------------
__device__ __forceinline__ void load_stage(uint32_t sbase,
                                           const float* __restrict__ adj,
                                           const float* __restrict__ z,
                                           const float* __restrict__ treat,
                                           int a_idx, int row0, int gk, int tid) {
    int q  = tid & 7;
    int rb = tid >> 3;

    // A: 128 rows x 128B, swizzle q ^ (row & 7); whole lines per warp-op
#pragma unroll
    for (int i = 0; i < 4; i++) {
        int r = i * 32 + rb;
        const float* src = adj + (long long)(row0 + r) * NN + gk + q * 4;
        uint32_t dst = sbase + r * 128 + (uint32_t)((q ^ (r & 7)) << 4);
        int sz = (row0 + r < NN) ? 16 : 0;
        asm volatile("cp.async.cg.shared.global.L2::256B [%0], [%1], 16, %2;\n"
                     :: "r"(dst), "l"(src), "r"(sz));
    }
    // B: 32 k-rows x 128B of z, row stride 160B in smem (no swizzle needed)
    {
        const float* src = z + (long long)(gk + rb) * HID + q * 4;
        uint32_t dst = sbase + BOFF + rb * BSTRIDE + q * 16;
        asm volatile("cp.async.cg.shared.global [%0], [%1], 16;\n"
                     :: "r"(dst), "l"(src));
    }
    // a_t column (col 32): 4-byte gather, L2-resident hot region
    if (tid < 32) {
        const float* src = treat + (long long)(gk + tid) * TSTEPS + a_idx;
        uint32_t dst = sbase + BOFF + tid * BSTRIDE + 128;
        asm volatile("cp.async.ca.shared.global [%0], [%1], 4;\n"
                     :: "r"(dst), "l"(src));
    }
}

// ---------------------------------------------------------------------------
// Kernel 1: tf32 mma.sync GEMM, C_part = adj @ [z | a_t]  (B = raw inputs!)
// ---------------------------------------------------------------------------
__global__ void __launch_bounds__(256, 2)
gemm_mma_kernel(const float* __restrict__ adj,
                const float* __restrict__ z,
                const float* __restrict__ treat,
                const float* __restrict__ t) {
    extern __shared__ char dsm[];
    uint32_t sbase0 = (uint32_t)__cvta_generic_to_shared(dsm);
    int tid  = threadIdx.x;
    int warp = tid >> 5;
    int lane = tid & 31;
    int g    = lane >> 2;
    int tg   = lane & 3;

    int blk  = blockIdx.x / KSPLIT;
    int kc   = blockIdx.x - blk * KSPLIT;
    int row0 = blk * TM;
    int k0   = kc * KITEM;

    int a_idx = (int)(t[0] * (float)(TSTEPS - 1));
    a_idx = min(max(a_idx, 0), TSTEPS - 1);

    // zero B pad bytes [132,160) of every row, every stage (never rewritten)
    for (int i = tid; i < NSTAGES * 32 * 7; i += 256) {
        int st = i / 224, rem = i - st * 224;
        int r = rem / 7, w = rem - r * 7;
        uint32_t addr = sbase0 + st * STAGE_BYTES + BOFF + r * BSTRIDE + 132 + w * 4;
        asm volatile("st.shared.u32 [%0], %1;" :: "r"(addr), "r"(0u));
    }
    __syncthreads();

    // prologue: fill 4 of 5 stages
#pragma unroll
    for (int p = 0; p < NSTAGES - 1; p++) {
        load_stage(sbase0 + p * STAGE_BYTES, adj, z, treat, a_idx,
                   row0, k0 + p * 32, tid);
        asm volatile("cp.async.commit_group;\n" ::: "memory");
    }

    float acc[NT][4];
#pragma unroll
    for (int n = 0; n < NT; n++)
#pragma unroll
        for (int i = 0; i < 4; i++) acc[n][i] = 0.f;

    const uint32_t aoff = (uint32_t)(warp * 16 + g) * 128 + tg * 4;
    const uint32_t boff = (uint32_t)BOFF + tg * BSTRIDE + g * 4;  // B[k=tg][n=g]

    for (int c = 0; c < NCHUNK; c++) {
        asm volatile("cp.async.wait_group 3;\n" ::: "memory");
        __syncthreads();

        if (c + NSTAGES - 1 < NCHUNK)
            load_stage(sbase0 + ((c + NSTAGES - 1) % NSTAGES) * STAGE_BYTES,
                       adj, z, treat, a_idx, row0,
                       k0 + (c + NSTAGES - 1) * 32, tid);
        asm volatile("cp.async.commit_group;\n" ::: "memory");

        const char* st = dsm + (c % NSTAGES) * STAGE_BYTES;
#pragma unroll
        for (int ks = 0; ks < 4; ks++) {
            uint32_t q0 = (uint32_t)(((2 * ks) ^ g) << 4);
            uint32_t q1 = (uint32_t)(((2 * ks + 1) ^ g) << 4);

            uint32_t a0 = *(const uint32_t*)(st + aoff + q0);
            uint32_t a2 = *(const uint32_t*)(st + aoff + q1);
            uint32_t a1 = *(const uint32_t*)(st + aoff + 1024 + q0);
            uint32_t a3 = *(const uint32_t*)(st + aoff + 1024 + q1);
#pragma unroll
            for (int nt = 0; nt < NT; nt++) {
                // B[k = 8ks+tg][n = nt*8+g], b1 at k+4
                uint32_t b0 = *(const uint32_t*)(st + boff + ks * (8 * BSTRIDE) +
                                                 nt * 32);
                uint32_t b1 = *(const uint32_t*)(st + boff + ks * (8 * BSTRIDE) +
                                                 nt * 32 + 4 * BSTRIDE);
                asm volatile(
                    "mma.sync.aligned.m16n8k8.row.col.f32.tf32.tf32.f32 "
                    "{%0,%1,%2,%3}, {%4,%5,%6,%7}, {%8,%9}, {%0,%1,%2,%3};\n"
                    : "+f"(acc[nt][0]), "+f"(acc[nt][1]),
                      "+f"(acc[nt][2]), "+f"(acc[nt][3])
                    : "r"(a0), "r"(a1), "r"(a2), "r"(a3), "r"(b0), "r"(b1));
            }
        }
    }

    // store split-K partial: [128 rows x 40 cols]
    float* part = g_part + (long long)kc * (NN * NCOLS);
    int r_lo = row0 + warp * 16 + g;
    int r_hi = r_lo + 8;
#pragma unroll
    for (int nt = 0; nt < NT; nt++) {
        int colb = nt * 8 + 2 * tg;
        if (r_lo < NN)
            *(float2*)(part + (long long)r_lo * NCOLS + colb) =
                make_float2(acc[nt][0], acc[nt][1]);
        if (r_hi < NN)
            *(float2*)(part + (long long)r_hi * NCOLS + colb) =
                make_float2(acc[nt][2], acc[nt][3]);
    }
}

// ---------------------------------------------------------------------------
// Kernel 2: out = relu( (sum_kc C_part)[.,0:33] @ W + b )
// One row per thread; W broadcast from smem; 33x32 FMA per thread.
// ---------------------------------------------------------------------------
__global__ void reduce_w_relu_kernel(float* __restrict__ out,
                                     const float* __restrict__ W,
                                     const float* __restrict__ bias) {
    __shared__ float Ws[33 * 32];
    __shared__ float Bs[32];
    int tid = threadIdx.x;
    for (int i = tid; i < 33 * 32; i += 256) Ws[i] = W[i];
    if (tid < 32) Bs[tid] = bias[tid];
    __syncthreads();

    int row = blockIdx.x * 256 + tid;
    if (row >= NN) return;

    const float* p0 = g_part + (long long)row * NCOLS;
    const float* p1 = p0 + (long long)NN * NCOLS;
    const float* p2 = p1 + (long long)NN * NCOLS;

    float c[33];
#pragma unroll
    for (int j = 0; j < 8; j++) {
        float4 v0 = ((const float4*)p0)[j];
        float4 v1 = ((const float4*)p1)[j];
        float4 v2 = ((const float4*)p2)[j];
        c[j * 4 + 0] = v0.x + v1.x + v2.x;
        c[j * 4 + 1] = v0.y + v1.y + v2.y;
        c[j * 4 + 2] = v0.z + v1.z + v2.z;
        c[j * 4 + 3] = v0.w + v1.w + v2.w;
    }
    c[32] = p0[32] + p1[32] + p2[32];

    float acc[32];
#pragma unroll
    for (int h = 0; h < 32; h++) acc[h] = Bs[h];
#pragma unroll
    for (int k = 0; k < 33; k++) {
        float ck = c[k];
#pragma unroll
        for (int h = 0; h < 32; h++)
            acc[h] = fmaf(ck, Ws[k * 32 + h], acc[h]);
    }
    float4* dst = (float4*)(out + (long long)row * HID);
#pragma unroll
    for (int j = 0; j < 8; j++) {
        float4 r;
        r.x = fmaxf(acc[j * 4 + 0], 0.f);
        r.y = fmaxf(acc[j * 4 + 1], 0.f);
        r.z = fmaxf(acc[j * 4 + 2], 0.f);
        r.w = fmaxf(acc[j * 4 + 3], 0.f);
        dst[j] = r;
    }
}

// ---------------------------------------------------------------------------
extern "C" void kernel_launch(void* const* d_in, const int* in_sizes, int n_in,
                              void* d_out, int out_size) {
    (void)in_sizes; (void)n_in; (void)out_size;
    const float* t     = (const float*)d_in[0];
    const float* z     = (const float*)d_in[1];
    const float* adj   = (const float*)d_in[2];
    const float* treat = (const float*)d_in[3];
    const float* W     = (const float*)d_in[4];
    const float* b     = (const float*)d_in[5];
    float* out = (float*)d_out;

    cudaFuncSetAttribute(gemm_mma_kernel,
                         cudaFuncAttributeMaxDynamicSharedMemorySize, SMEM_REQ);

    gemm_mma_kernel<<<NITEMS, 256, SMEM_REQ>>>(adj, z, treat, t);
    reduce_w_relu_kernel<<<(NN + 255) / 256, 256>>>(out, W, b);
}

// round 11
// speedup vs baseline: 1.0900x; 1.0900x over previous
#include <cuda_runtime.h>
#include <cstdint>

#define NN      12000
#define HID     32
#define TSTEPS  50
#define TM      128
#define KSPLIT  3
#define KITEM   4000             // K per work item (KSPLIT*KITEM == NN)
#define NCHUNK  125              // KITEM / 32
#define NBLK    94               // ceil(12000/128)
#define NITEMS  (NBLK * KSPLIT)  // 282 CTAs, one item each
#define NSTAGES 5
#define STAGE_BYTES 20480        // A: 128*32*4 = 16384  +  B: 32*32*4 = 4096
#define SMEM_REQ (NSTAGES * STAGE_BYTES)

__device__ float g_suppT[HID * NN];           // support^T: [32][12000], tf32-rounded
__device__ float g_part[KSPLIT * NN * HID];   // split-K partials (deterministic)

// ---------------------------------------------------------------------------
// Kernel 1: support = [z | a_t] @ W, transposed + tf32-rounded output.
// Single wave: 94 CTAs x 256 thr, 16 rows/warp (16 independent chains).
// Per-row FMA order identical to prior rounds -> bit-identical output.
// ---------------------------------------------------------------------------
__global__ void __launch_bounds__(256)
support_kernel(const float* __restrict__ t,
               const float* __restrict__ z,
               const float* __restrict__ treat,
               const float* __restrict__ W) {
    __shared__ float Ws[33 * 32];
    __shared__ float S[128][33];   // stride 33 -> conflict-free transpose
    int tid  = threadIdx.x;
    int lane = tid & 31;
    int warp = tid >> 5;

    for (int i = tid; i < 33 * 32; i += 256) Ws[i] = W[i];

    int a_idx = (int)(t[0] * (float)(TSTEPS - 1));
    a_idx = min(max(a_idx, 0), TSTEPS - 1);

    int row0 = blockIdx.x * 128;        // 94*128 = 12032 >= 12000
    int r0   = warp * 16;               // warp's 16 rows within block
    int nrows = min(16, NN - (row0 + r0));   // <=0 for fully-OOB warps
    __syncthreads();

    if (nrows > 0) {
        float zv[16], acc[16];
        // gather phase: 16 independent z loads + 16 treat broadcasts
        for (int j = 0; j < 16; j++) {
            if (j < nrows) {
                int row = row0 + r0 + j;
                zv[j]  = z[row * 32 + lane];
                acc[j] = treat[row * TSTEPS + a_idx] * Ws[32 * 32 + lane];
            } else { zv[j] = 0.f; acc[j] = 0.f; }
        }
#pragma unroll
        for (int k = 0; k < 32; k++) {
            float w = Ws[k * 32 + lane];
#pragma unroll
            for (int j = 0; j < 16; j++) {
                float zk = __shfl_sync(0xffffffffu, zv[j], k);
                acc[j] = fmaf(zk, w, acc[j]);
            }
        }
#pragma unroll
        for (int j = 0; j < 16; j++) {
            uint32_t bits;
            asm("cvt.rna.tf32.f32 %0, %1;" : "=r"(bits) : "f"(acc[j]));
            S[r0 + j][lane] = __uint_as_float(bits);
        }
    }
    __syncthreads();

    // coalesced transposed store: 128 rows x 32 cols, 16 elems/thread
#pragma unroll
    for (int j = 0; j < 16; j++) {
        int idx = tid + 256 * j;        // 0..4095
        int col = idx >> 7;             // 0..31
        int r   = idx & 127;
        int row = row0 + r;
        if (row < NN)
            g_suppT[col * NN + row] = S[r][col];
    }
}

// ---------------------------------------------------------------------------
// cp.async stage loads: line-complete per warp-op (whole 128B lines).
// ---------------------------------------------------------------------------
__device__ __forceinline__ void load_A(uint32_t sbase, const float* __restrict__ adj,
                                       int row0, int gk, int tid) {
    int q  = tid & 7;
    int rb = tid >> 3;
#pragma unroll
    for (int i = 0; i < 4; i++) {
        int r = i * 32 + rb;
        const float* src = adj + (long long)(row0 + r) * NN + gk + q * 4;
        uint32_t dst = sbase + r * 128 + (uint32_t)((q ^ (r & 7)) << 4);
        int sz = (row0 + r < NN) ? 16 : 0;
        asm volatile("cp.async.cg.shared.global.L2::256B [%0], [%1], 16, %2;\n"
                     :: "r"(dst), "l"(src), "r"(sz));
    }
}

__device__ __forceinline__ void load_B(uint32_t sbase, int gk, int tid) {
    int q = tid & 7;
    int c = tid >> 3;
    const float* src = g_suppT + (long long)c * NN + gk + q * 4;
    uint32_t dst = sbase + 16384 + c * 128 + (uint32_t)((q ^ (c & 7)) << 4);
    asm volatile("cp.async.cg.shared.global.L2::256B [%0], [%1], 16;\n"
                 :: "r"(dst), "l"(src));
}

// ---------------------------------------------------------------------------
// Kernel 2: tf32 mma.sync GEMM — exact round-5 body (103.2us build).
// ---------------------------------------------------------------------------
__global__ void __launch_bounds__(256, 2)
gemm_mma_kernel(const float* __restrict__ adj) {
    extern __shared__ char dsm[];
    uint32_t sbase0 = (uint32_t)__cvta_generic_to_shared(dsm);
    int tid  = threadIdx.x;
    int warp = tid >> 5;
    int lane = tid & 31;
    int g    = lane >> 2;
    int tg   = lane & 3;

    int blk  = blockIdx.x / KSPLIT;
    int kc   = blockIdx.x - blk * KSPLIT;
    int row0 = blk * TM;
    int k0   = kc * KITEM;

    float acc[4][4];
#pragma unroll
    for (int n = 0; n < 4; n++)
#pragma unroll
        for (int i = 0; i < 4; i++) acc[n][i] = 0.f;

    const uint32_t aoff = (uint32_t)(warp * 16 + g) * 128 + tg * 4;
    const uint32_t boff = 16384u + (uint32_t)g * 128 + tg * 4;

#pragma unroll
    for (int p = 0; p < NSTAGES - 1; p++) {
        uint32_t sb = sbase0 + p * STAGE_BYTES;
        load_A(sb, adj, row0, k0 + p * 32, tid);
        load_B(sb, k0 + p * 32, tid);
        asm volatile("cp.async.commit_group;\n" ::: "memory");
    }

    for (int c = 0; c < NCHUNK; c++) {
        asm volatile("cp.async.wait_group 3;\n" ::: "memory");
        __syncthreads();

        if (c + NSTAGES - 1 < NCHUNK) {
            uint32_t sb = sbase0 + ((c + NSTAGES - 1) % NSTAGES) * STAGE_BYTES;
            load_A(sb, adj, row0, k0 + (c + NSTAGES - 1) * 32, tid);
            load_B(sb, k0 + (c + NSTAGES - 1) * 32, tid);
        }
        asm volatile("cp.async.commit_group;\n" ::: "memory");

        const char* st = dsm + (c % NSTAGES) * STAGE_BYTES;
#pragma unroll
        for (int ks = 0; ks < 4; ks++) {
            uint32_t q0 = (uint32_t)(((2 * ks) ^ g) << 4);
            uint32_t q1 = (uint32_t)(((2 * ks + 1) ^ g) << 4);

            uint32_t a0 = *(const uint32_t*)(st + aoff + q0);
            uint32_t a2 = *(const uint32_t*)(st + aoff + q1);
            uint32_t a1 = *(const uint32_t*)(st + aoff + 1024 + q0);
            uint32_t a3 = *(const uint32_t*)(st + aoff + 1024 + q1);
#pragma unroll
            for (int nt = 0; nt < 4; nt++) {
                uint32_t b0 = *(const uint32_t*)(st + boff + nt * 1024 + q0);
                uint32_t b1 = *(const uint32_t*)(st + boff + nt * 1024 + q1);
                asm volatile(
                    "mma.sync.aligned.m16n8k8.row.col.f32.tf32.tf32.f32 "
                    "{%0,%1,%2,%3}, {%4,%5,%6,%7}, {%8,%9}, {%0,%1,%2,%3};\n"
                    : "+f"(acc[nt][0]), "+f"(acc[nt][1]),
                      "+f"(acc[nt][2]), "+f"(acc[nt][3])
                    : "r"(a0), "r"(a1), "r"(a2), "r"(a3), "r"(b0), "r"(b1));
            }
        }
    }

    float* part = g_part + (long long)kc * (NN * HID);
    int r_lo = row0 + warp * 16 + g;
    int r_hi = r_lo + 8;
#pragma unroll
    for (int nt = 0; nt < 4; nt++) {
        int colb = nt * 8 + 2 * tg;
        if (r_lo < NN)
            *(float2*)(part + (long long)r_lo * HID + colb) =
                make_float2(acc[nt][0], acc[nt][1]);
        if (r_hi < NN)
            *(float2*)(part + (long long)r_hi * HID + colb) =
                make_float2(acc[nt][2], acc[nt][3]);
    }
}

// ---------------------------------------------------------------------------
// Kernel 3: out = relu(sum_kc part[kc] + b)
// ---------------------------------------------------------------------------
__global__ void reduce_relu_kernel(float* __restrict__ out,
                                   const float* __restrict__ b) {
    int i4 = blockIdx.x * blockDim.x + threadIdx.x;
    if (i4 >= NN * HID / 4) return;
    const float4* p = (const float4*)g_part;
    float4 s = ((const float4*)b)[i4 & 7];
#pragma unroll
    for (int kc = 0; kc < KSPLIT; kc++) {
        float4 v = p[(long long)kc * (NN * HID / 4) + i4];
        s.x += v.x; s.y += v.y; s.z += v.z; s.w += v.w;
    }
    float4 r;
    r.x = fmaxf(s.x, 0.f);
    r.y = fmaxf(s.y, 0.f);
    r.z = fmaxf(s.z, 0.f);
    r.w = fmaxf(s.w, 0.f);
    ((float4*)out)[i4] = r;
}

// ---------------------------------------------------------------------------
extern "C" void kernel_launch(void* const* d_in, const int* in_sizes, int n_in,
                              void* d_out, int out_size) {
    (void)in_sizes; (void)n_in; (void)out_size;
    const float* t     = (const float*)d_in[0];
    const float* z     = (const float*)d_in[1];
    const float* adj   = (const float*)d_in[2];
    const float* treat = (const float*)d_in[3];
    const float* W     = (const float*)d_in[4];
    const float* b     = (const float*)d_in[5];
    float* out = (float*)d_out;

    cudaFuncSetAttribute(gemm_mma_kernel,
                         cudaFuncAttributeMaxDynamicSharedMemorySize, SMEM_REQ);

    support_kernel<<<NBLK, 256>>>(t, z, treat, W);
    gemm_mma_kernel<<<NITEMS, 256, SMEM_REQ>>>(adj);
    reduce_relu_kernel<<<(NN * HID / 4 + 255) / 256, 256>>>(out, b);
}

// round 12
// speedup vs baseline: 1.1089x; 1.0173x over previous
#include <cuda_runtime.h>
#include <cstdint>

#define NN      12000
#define HID     32
#define TSTEPS  50
#define TM      128
#define KSPLIT  3
#define KITEM   4000             // K per work item (KSPLIT*KITEM == NN)
#define NCHUNK  125              // KITEM / 32
#define NBLK    94               // ceil(12000/128)
#define NITEMS  (NBLK * KSPLIT)  // 282 CTAs, one item each
#define NSTAGES 5
#define STAGE_BYTES 20480        // A: 128*32*4 = 16384  +  B: 32*32*4 = 4096
#define SMEM_REQ (NSTAGES * STAGE_BYTES)

__device__ float g_suppT[HID * NN];           // support^T: [32][12000], tf32-rounded
__device__ float g_part[KSPLIT * NN * HID];   // split-K partials (deterministic)

// ---------------------------------------------------------------------------
// Kernel 1: support = [z | a_t] @ W, transposed + tf32-rounded output.
// Round-4 variant: grid 375, 4 rows/warp (fastest measured: 7.58us).
// ---------------------------------------------------------------------------
__global__ void support_kernel(const float* __restrict__ t,
                               const float* __restrict__ z,
                               const float* __restrict__ treat,
                               const float* __restrict__ W) {
    __shared__ float Ws[33 * 32];
    __shared__ float S[32][33];    // stride 33 -> conflict-free transpose
    int tid = threadIdx.x;
    for (int i = tid; i < 33 * 32; i += blockDim.x) Ws[i] = W[i];
    __syncthreads();

    int a_idx = (int)(t[0] * (float)(TSTEPS - 1));
    a_idx = min(max(a_idx, 0), TSTEPS - 1);

    int lane = tid & 31;
    int warp = tid >> 5;
    int row0 = blockIdx.x * 32;         // grid = 375, 375*32 == 12000
    int r0   = warp * 4;                // warp's 4 rows within block

    float zv[4], acc[4];
#pragma unroll
    for (int j = 0; j < 4; j++) {
        int row = row0 + r0 + j;
        zv[j]  = z[row * 32 + lane];
        acc[j] = treat[row * TSTEPS + a_idx] * Ws[32 * 32 + lane];
    }
#pragma unroll
    for (int k = 0; k < 32; k++) {
        float w = Ws[k * 32 + lane];
#pragma unroll
        for (int j = 0; j < 4; j++) {
            float zk = __shfl_sync(0xffffffffu, zv[j], k);
            acc[j] = fmaf(zk, w, acc[j]);
        }
    }
#pragma unroll
    for (int j = 0; j < 4; j++) {
        uint32_t bits;
        asm("cvt.rna.tf32.f32 %0, %1;" : "=r"(bits) : "f"(acc[j]));
        S[r0 + j][lane] = __uint_as_float(bits);
    }
    __syncthreads();

#pragma unroll
    for (int j = 0; j < 4; j++) {
        int idx = tid + 256 * j;
        int col = idx >> 5;
        int r   = idx & 31;
        g_suppT[col * NN + row0 + r] = S[r][col];
    }
}

// ---------------------------------------------------------------------------
// cp.async stage loads: line-complete per warp-op (whole 128B lines).
// ---------------------------------------------------------------------------
__device__ __forceinline__ void load_A(uint32_t sbase, const float* __restrict__ adj,
                                       int row0, int gk, int tid) {
    int q  = tid & 7;
    int rb = tid >> 3;
#pragma unroll
    for (int i = 0; i < 4; i++) {
        int r = i * 32 + rb;
        const float* src = adj + (long long)(row0 + r) * NN + gk + q * 4;
        uint32_t dst = sbase + r * 128 + (uint32_t)((q ^ (r & 7)) << 4);
        int sz = (row0 + r < NN) ? 16 : 0;
        asm volatile("cp.async.cg.shared.global.L2::256B [%0], [%1], 16, %2;\n"
                     :: "r"(dst), "l"(src), "r"(sz));
    }
}

__device__ __forceinline__ void load_B(uint32_t sbase, int gk, int tid) {
    int q = tid & 7;
    int c = tid >> 3;
    const float* src = g_suppT + (long long)c * NN + gk + q * 4;
    uint32_t dst = sbase + 16384 + c * 128 + (uint32_t)((q ^ (c & 7)) << 4);
    asm volatile("cp.async.cg.shared.global.L2::256B [%0], [%1], 16;\n"
                 :: "r"(dst), "l"(src));
}

// ---------------------------------------------------------------------------
// Kernel 2: tf32 mma.sync GEMM — exact round-5 body; fires PDL trigger at
// the very end so the reduce kernel launches under the GEMM tail.
// ---------------------------------------------------------------------------
__global__ void __launch_bounds__(256, 2)
gemm_mma_kernel(const float* __restrict__ adj) {
    extern __shared__ char dsm[];
    uint32_t sbase0 = (uint32_t)__cvta_generic_to_shared(dsm);
    int tid  = threadIdx.x;
    int warp = tid >> 5;
    int lane = tid & 31;
    int g    = lane >> 2;
    int tg   = lane & 3;

    int blk  = blockIdx.x / KSPLIT;
    int kc   = blockIdx.x - blk * KSPLIT;
    int row0 = blk * TM;
    int k0   = kc * KITEM;

    float acc[4][4];
#pragma unroll
    for (int n = 0; n < 4; n++)
#pragma unroll
        for (int i = 0; i < 4; i++) acc[n][i] = 0.f;

    const uint32_t aoff = (uint32_t)(warp * 16 + g) * 128 + tg * 4;
    const uint32_t boff = 16384u + (uint32_t)g * 128 + tg * 4;

#pragma unroll
    for (int p = 0; p < NSTAGES - 1; p++) {
        uint32_t sb = sbase0 + p * STAGE_BYTES;
        load_A(sb, adj, row0, k0 + p * 32, tid);
        load_B(sb, k0 + p * 32, tid);
        asm volatile("cp.async.commit_group;\n" ::: "memory");
    }

    for (int c = 0; c < NCHUNK; c++) {
        asm volatile("cp.async.wait_group 3;\n" ::: "memory");
        __syncthreads();

        if (c + NSTAGES - 1 < NCHUNK) {
            uint32_t sb = sbase0 + ((c + NSTAGES - 1) % NSTAGES) * STAGE_BYTES;
            load_A(sb, adj, row0, k0 + (c + NSTAGES - 1) * 32, tid);
            load_B(sb, k0 + (c + NSTAGES - 1) * 32, tid);
        }
        asm volatile("cp.async.commit_group;\n" ::: "memory");

        const char* st = dsm + (c % NSTAGES) * STAGE_BYTES;
#pragma unroll
        for (int ks = 0; ks < 4; ks++) {
            uint32_t q0 = (uint32_t)(((2 * ks) ^ g) << 4);
            uint32_t q1 = (uint32_t)(((2 * ks + 1) ^ g) << 4);

            uint32_t a0 = *(const uint32_t*)(st + aoff + q0);
            uint32_t a2 = *(const uint32_t*)(st + aoff + q1);
            uint32_t a1 = *(const uint32_t*)(st + aoff + 1024 + q0);
            uint32_t a3 = *(const uint32_t*)(st + aoff + 1024 + q1);
#pragma unroll
            for (int nt = 0; nt < 4; nt++) {
                uint32_t b0 = *(const uint32_t*)(st + boff + nt * 1024 + q0);
                uint32_t b1 = *(const uint32_t*)(st + boff + nt * 1024 + q1);
                asm volatile(
                    "mma.sync.aligned.m16n8k8.row.col.f32.tf32.tf32.f32 "
                    "{%0,%1,%2,%3}, {%4,%5,%6,%7}, {%8,%9}, {%0,%1,%2,%3};\n"
                    : "+f"(acc[nt][0]), "+f"(acc[nt][1]),
                      "+f"(acc[nt][2]), "+f"(acc[nt][3])
                    : "r"(a0), "r"(a1), "r"(a2), "r"(a3), "r"(b0), "r"(b1));
            }
        }
    }

    float* part = g_part + (long long)kc * (NN * HID);
    int r_lo = row0 + warp * 16 + g;
    int r_hi = r_lo + 8;
#pragma unroll
    for (int nt = 0; nt < 4; nt++) {
        int colb = nt * 8 + 2 * tg;
        if (r_lo < NN)
            *(float2*)(part + (long long)r_lo * HID + colb) =
                make_float2(acc[nt][0], acc[nt][1]);
        if (r_hi < NN)
            *(float2*)(part + (long long)r_hi * HID + colb) =
                make_float2(acc[nt][2], acc[nt][3]);
    }

    // make partial stores visible, then release the dependent reduce launch
    asm volatile("membar.gl;\n" ::: "memory");
    asm volatile("griddepcontrol.launch_dependents;\n" ::: "memory");
}

// ---------------------------------------------------------------------------
// Kernel 3: out = relu(sum_kc part[kc] + b). PDL-dependent on the GEMM.
// ---------------------------------------------------------------------------
__global__ void reduce_relu_kernel(float* __restrict__ out,
                                   const float* __restrict__ b) {
    asm volatile("griddepcontrol.wait;\n" ::: "memory");
    int i4 = blockIdx.x * blockDim.x + threadIdx.x;
    if (i4 >= NN * HID / 4) return;
    const float4* p = (const float4*)g_part;
    float4 s = ((const float4*)b)[i4 & 7];
#pragma unroll
    for (int kc = 0; kc < KSPLIT; kc++) {
        float4 v = p[(long long)kc * (NN * HID / 4) + i4];
        s.x += v.x; s.y += v.y; s.z += v.z; s.w += v.w;
    }
    float4 r;
    r.x = fmaxf(s.x, 0.f);
    r.y = fmaxf(s.y, 0.f);
    r.z = fmaxf(s.z, 0.f);
    r.w = fmaxf(s.w, 0.f);
    ((float4*)out)[i4] = r;
}

// ---------------------------------------------------------------------------
extern "C" void kernel_launch(void* const* d_in, const int* in_sizes, int n_in,
                              void* d_out, int out_size) {
    (void)in_sizes; (void)n_in; (void)out_size;
    const float* t     = (const float*)d_in[0];
    const float* z     = (const float*)d_in[1];
    const float* adj   = (const float*)d_in[2];
    const float* treat = (const float*)d_in[3];
    const float* W     = (const float*)d_in[4];
    const float* b     = (const float*)d_in[5];
    float* out = (float*)d_out;

    cudaFuncSetAttribute(gemm_mma_kernel,
                         cudaFuncAttributeMaxDynamicSharedMemorySize, SMEM_REQ);

    support_kernel<<<NN / 32, 256>>>(t, z, treat, W);
    gemm_mma_kernel<<<NITEMS, 256, SMEM_REQ>>>(adj);

    cudaLaunchConfig_t cfg = {};
    cfg.gridDim  = dim3((NN * HID / 4 + 255) / 256, 1, 1);
    cfg.blockDim = dim3(256, 1, 1);
    cfg.dynamicSmemBytes = 0;
    cfg.stream = 0;
    cudaLaunchAttribute attrs[1];
    attrs[0].id = cudaLaunchAttributeProgrammaticStreamSerialization;
    attrs[0].val.programmaticStreamSerializationAllowed = 1;
    cfg.attrs = attrs;
    cfg.numAttrs = 1;
    cudaLaunchKernelEx(&cfg, reduce_relu_kernel, out, (const float*)b);
}

// round 13
// speedup vs baseline: 1.1116x; 1.0024x over previous
#include <cuda_runtime.h>
#include <cstdint>

#define NN      12000
#define HID     32
#define TSTEPS  50
#define TM      128
#define KSPLIT  3
#define KITEM   4000             // K per work item (KSPLIT*KITEM == NN)
#define NCHUNK  125              // KITEM / 32
#define NBLK    94               // ceil(12000/128)
#define NITEMS  (NBLK * KSPLIT)  // 282 CTAs, one item each
#define NSTAGES 5
#define BOFF    16384            // B region offset within a stage
#define BSTRIDE 160              // B row stride in bytes (conflict-free, no swizzle)
#define STAGE_BYTES (BOFF + 32 * BSTRIDE)    // 21504
#define SMEM_REQ (NSTAGES * STAGE_BYTES)     // 107520

__device__ float g_supp[NN * HID];            // support, ROW-major [node][h], tf32-rounded
__device__ float g_part[KSPLIT * NN * HID];   // split-K partials (deterministic)

// ---------------------------------------------------------------------------
// Kernel 1: support = [z | a_t] @ W, row-major output, direct register->GMEM
// stores (no transpose pass). Grid 375, 4 rows/warp (empirical optimum).
// ---------------------------------------------------------------------------
__global__ void support_kernel(const float* __restrict__ t,
                               const float* __restrict__ z,
                               const float* __restrict__ treat,
                               const float* __restrict__ W) {
    __shared__ float Ws[33 * 32];
    int tid = threadIdx.x;
    for (int i = tid; i < 33 * 32; i += blockDim.x) Ws[i] = W[i];
    __syncthreads();

    int a_idx = (int)(t[0] * (float)(TSTEPS - 1));
    a_idx = min(max(a_idx, 0), TSTEPS - 1);

    int lane = tid & 31;
    int warp = tid >> 5;
    int row0 = blockIdx.x * 32 + warp * 4;   // grid = 375, 375*32 == 12000

    float zv[4], acc[4];
#pragma unroll
    for (int j = 0; j < 4; j++) {
        int row = row0 + j;
        zv[j]  = z[row * 32 + lane];
        acc[j] = treat[row * TSTEPS + a_idx] * Ws[32 * 32 + lane];
    }
#pragma unroll
    for (int k = 0; k < 32; k++) {
        float w = Ws[k * 32 + lane];
#pragma unroll
        for (int j = 0; j < 4; j++) {
            float zk = __shfl_sync(0xffffffffu, zv[j], k);
            acc[j] = fmaf(zk, w, acc[j]);
        }
    }
#pragma unroll
    for (int j = 0; j < 4; j++) {
        uint32_t bits;
        asm("cvt.rna.tf32.f32 %0, %1;" : "=r"(bits) : "f"(acc[j]));
        g_supp[(row0 + j) * 32 + lane] = __uint_as_float(bits);  // coalesced 128B/row
    }
}

// ---------------------------------------------------------------------------
// Stage loads. A: swizzled, line-complete warp-ops (as in the 103us build).
// B: rows gk..gk+31 of row-major g_supp = ONE contiguous 4KB block.
// ---------------------------------------------------------------------------
__device__ __forceinline__ void load_A(uint32_t sbase, const float* __restrict__ adj,
                                       int row0, int gk, int tid) {
    int q  = tid & 7;
    int rb = tid >> 3;
#pragma unroll
    for (int i = 0; i < 4; i++) {
        int r = i * 32 + rb;
        const float* src = adj + (long long)(row0 + r) * NN + gk + q * 4;
        uint32_t dst = sbase + r * 128 + (uint32_t)((q ^ (r & 7)) << 4);
        int sz = (row0 + r < NN) ? 16 : 0;
        asm volatile("cp.async.cg.shared.global.L2::256B [%0], [%1], 16, %2;\n"
                     :: "r"(dst), "l"(src), "r"(sz));
    }
}

__device__ __forceinline__ void load_B(uint32_t sbase, int gk, int tid) {
    int q  = tid & 7;               // 16B chunk within row
    int rb = tid >> 3;              // k-row 0..31
    const float* src = g_supp + (long long)(gk + rb) * HID + q * 4;  // contiguous 4KB
    uint32_t dst = sbase + BOFF + rb * BSTRIDE + q * 16;
    asm volatile("cp.async.cg.shared.global [%0], [%1], 16;\n"
                 :: "r"(dst), "l"(src));
}

// ---------------------------------------------------------------------------
// Kernel 2: tf32 mma.sync GEMM — round-5 A-path/mainloop; B row-major tile.
// ---------------------------------------------------------------------------
__global__ void __launch_bounds__(256, 2)
gemm_mma_kernel(const float* __restrict__ adj) {
    extern __shared__ char dsm[];
    uint32_t sbase0 = (uint32_t)__cvta_generic_to_shared(dsm);
    int tid  = threadIdx.x;
    int warp = tid >> 5;
    int lane = tid & 31;
    int g    = lane >> 2;
    int tg   = lane & 3;

    int blk  = blockIdx.x / KSPLIT;
    int kc   = blockIdx.x - blk * KSPLIT;
    int row0 = blk * TM;
    int k0   = kc * KITEM;

    float acc[4][4];
#pragma unroll
    for (int n = 0; n < 4; n++)
#pragma unroll
        for (int i = 0; i < 4; i++) acc[n][i] = 0.f;

    const uint32_t aoff = (uint32_t)(warp * 16 + g) * 128 + tg * 4;
    // B row-major: frag element (k=8ks+tg, n=nt*8+g) at BOFF + k*160 + n*4
    const uint32_t boff = (uint32_t)BOFF + tg * BSTRIDE + g * 4;

#pragma unroll
    for (int p = 0; p < NSTAGES - 1; p++) {
        uint32_t sb = sbase0 + p * STAGE_BYTES;
        load_A(sb, adj, row0, k0 + p * 32, tid);
        load_B(sb, k0 + p * 32, tid);
        asm volatile("cp.async.commit_group;\n" ::: "memory");
    }

    for (int c = 0; c < NCHUNK; c++) {
        asm volatile("cp.async.wait_group 3;\n" ::: "memory");
        __syncthreads();

        if (c + NSTAGES - 1 < NCHUNK) {
            uint32_t sb = sbase0 + ((c + NSTAGES - 1) % NSTAGES) * STAGE_BYTES;
            load_A(sb, adj, row0, k0 + (c + NSTAGES - 1) * 32, tid);
            load_B(sb, k0 + (c + NSTAGES - 1) * 32, tid);
        }
        asm volatile("cp.async.commit_group;\n" ::: "memory");

        const char* st = dsm + (c % NSTAGES) * STAGE_BYTES;
#pragma unroll
        for (int ks = 0; ks < 4; ks++) {
            uint32_t q0 = (uint32_t)(((2 * ks) ^ g) << 4);
            uint32_t q1 = (uint32_t)(((2 * ks + 1) ^ g) << 4);

            uint32_t a0 = *(const uint32_t*)(st + aoff + q0);
            uint32_t a2 = *(const uint32_t*)(st + aoff + q1);
            uint32_t a1 = *(const uint32_t*)(st + aoff + 1024 + q0);
            uint32_t a3 = *(const uint32_t*)(st + aoff + 1024 + q1);
#pragma unroll
            for (int nt = 0; nt < 4; nt++) {
                uint32_t b0 = *(const uint32_t*)(st + boff + ks * (8 * BSTRIDE) +
                                                 nt * 32);
                uint32_t b1 = *(const uint32_t*)(st + boff + ks * (8 * BSTRIDE) +
                                                 nt * 32 + 4 * BSTRIDE);
                asm volatile(
                    "mma.sync.aligned.m16n8k8.row.col.f32.tf32.tf32.f32 "
                    "{%0,%1,%2,%3}, {%4,%5,%6,%7}, {%8,%9}, {%0,%1,%2,%3};\n"
                    : "+f"(acc[nt][0]), "+f"(acc[nt][1]),
                      "+f"(acc[nt][2]), "+f"(acc[nt][3])
                    : "r"(a0), "r"(a1), "r"(a2), "r"(a3), "r"(b0), "r"(b1));
            }
        }
    }

    float* part = g_part + (long long)kc * (NN * HID);
    int r_lo = row0 + warp * 16 + g;
    int r_hi = r_lo + 8;
#pragma unroll
    for (int nt = 0; nt < 4; nt++) {
        int colb = nt * 8 + 2 * tg;
        if (r_lo < NN)
            *(float2*)(part + (long long)r_lo * HID + colb) =
                make_float2(acc[nt][0], acc[nt][1]);
        if (r_hi < NN)
            *(float2*)(part + (long long)r_hi * HID + colb) =
                make_float2(acc[nt][2], acc[nt][3]);
    }
}

// ---------------------------------------------------------------------------
// Kernel 3: out = relu(sum_kc part[kc] + b)
// ---------------------------------------------------------------------------
__global__ void reduce_relu_kernel(float* __restrict__ out,
                                   const float* __restrict__ b) {
    int i4 = blockIdx.x * blockDim.x + threadIdx.x;
    if (i4 >= NN * HID / 4) return;
    const float4* p = (const float4*)g_part;
    float4 s = ((const float4*)b)[i4 & 7];
#pragma unroll
    for (int kc = 0; kc < KSPLIT; kc++) {
        float4 v = p[(long long)kc * (NN * HID / 4) + i4];
        s.x += v.x; s.y += v.y; s.z += v.z; s.w += v.w;
    }
    float4 r;
    r.x = fmaxf(s.x, 0.f);
    r.y = fmaxf(s.y, 0.f);
    r.z = fmaxf(s.z, 0.f);
    r.w = fmaxf(s.w, 0.f);
    ((float4*)out)[i4] = r;
}

// ---------------------------------------------------------------------------
extern "C" void kernel_launch(void* const* d_in, const int* in_sizes, int n_in,
                              void* d_out, int out_size) {
    (void)in_sizes; (void)n_in; (void)out_size;
    const float* t     = (const float*)d_in[0];
    const float* z     = (const float*)d_in[1];
    const float* adj   = (const float*)d_in[2];
    const float* treat = (const float*)d_in[3];
    const float* W     = (const float*)d_in[4];
    const float* b     = (const float*)d_in[5];
    float* out = (float*)d_out;

    cudaFuncSetAttribute(gemm_mma_kernel,
                         cudaFuncAttributeMaxDynamicSharedMemorySize, SMEM_REQ);

    support_kernel<<<NN / 32, 256>>>(t, z, treat, W);
    gemm_mma_kernel<<<NITEMS, 256, SMEM_REQ>>>(adj);
    reduce_relu_kernel<<<(NN * HID / 4 + 255) / 256, 256>>>(out, b);
}